// round 4
// baseline (speedup 1.0000x reference)
#include <cuda_runtime.h>
#include <cuda_bf16.h>

#define T_SEQ 2048
#define NB 2
#define NH 8
#define NS 32
#define DH 128
#define DMODEL 1024

__device__ float g_Q[NB*NH*T_SEQ*DH];
__device__ float g_K[NB*NH*T_SEQ*DH];
__device__ float g_V[NB*NH*T_SEQ*DH];
__device__ float g_QW[NB*NH*T_SEQ*NS];
__device__ float g_KW[NB*NH*T_SEQ*NS];
__device__ float g_O[NB*T_SEQ*DMODEL];
__device__ float g_P[(size_t)NB*NH*T_SEQ*T_SEQ];
__device__ float g_Sinv[NB*NH*T_SEQ];

__device__ __forceinline__ float fast_exp(float x) {
    float t = x * 1.4426950408889634f;
    t = fmaxf(t, -126.0f);
    float fi = floorf(t);
    float f = t - fi;
    float p = 1.5403530e-4f;
    p = fmaf(p, f, 1.3333558e-3f);
    p = fmaf(p, f, 9.6181291e-3f);
    p = fmaf(p, f, 5.5504109e-2f);
    p = fmaf(p, f, 2.4022651e-1f);
    p = fmaf(p, f, 6.9314718e-1f);
    p = fmaf(p, f, 1.0f);
    return p * __int_as_float(((int)fi + 127) << 23);
}

// split-pack: two fp32 -> (hi bf16x2, lo bf16x2), low half = f0. Exact: f = hi + lo + O(2^-16).
__device__ __forceinline__ void split_pack(float f0, float f1, unsigned& hi, unsigned& lo) {
    unsigned u0 = __float_as_uint(f0), u1 = __float_as_uint(f1);
    hi = __byte_perm(u0, u1, 0x7632);               // {u0.hi16, u1.hi16}, low=f0_hi
    float l0 = f0 - __uint_as_float(u0 & 0xffff0000u);
    float l1 = f1 - __uint_as_float(u1 & 0xffff0000u);
    asm("cvt.rn.bf16x2.f32 %0, %1, %2;" : "=r"(lo) : "f"(l1), "f"(l0));  // hi-half=l1, lo-half=l0
}

__device__ __forceinline__ void mma_bf16(float* d, const unsigned* a, unsigned b0, unsigned b1) {
    asm volatile(
        "mma.sync.aligned.m16n8k16.row.col.f32.bf16.bf16.f32 "
        "{%0,%1,%2,%3}, {%4,%5,%6,%7}, {%8,%9}, {%0,%1,%2,%3};"
        : "+f"(d[0]), "+f"(d[1]), "+f"(d[2]), "+f"(d[3])
        : "r"(a[0]), "r"(a[1]), "r"(a[2]), "r"(a[3]), "r"(b0), "r"(b1));
}

// Tensor GEMM: block 128x128, K-panel 16, 8 warps (warp tile 32x64).
// MODE 0: x@Wqkv+bqkv -> scatter g_Q/g_K/g_V  (A=x, lda=1024, N=3072)
// MODE 1: g_O@Wout+bout -> Cout               (lda=1024, N=1024)
// MODE 2: g_P@g_V * Sinv -> g_O               (per-bh batch, lda=2048, N=128)
template<int MODE>
__global__ void __launch_bounds__(256, 2) gemm_t_kernel(
    const float* __restrict__ Ain, const float* __restrict__ Bm,
    const float* __restrict__ bias, float* __restrict__ Cout,
    int N, int K)
{
    __shared__ unsigned As_hi[128][12], As_lo[128][12];   // [m][k-pairs], 16 halves pad 24
    __shared__ unsigned Bs_hi[128][12], Bs_lo[128][12];   // [n][k-pairs]
    __shared__ float Bf[16][132];                          // fp32 B staging [k][n]

    int t = threadIdx.x, warp = t >> 5, lane = t & 31;
    int g = lane >> 2, tig = lane & 3;
    int wm = warp >> 1, wn = warp & 1;

    int bh = blockIdx.y;                 // MODE 2 only
    int n0 = (MODE == 2) ? 0   : blockIdx.x * 128;
    int m0 = (MODE == 2) ? blockIdx.x * 128 : blockIdx.y * 128;

    const float* A; const float* B; int lda, ldb;
    if (MODE == 0) { A = Ain;  B = Bm; lda = DMODEL; ldb = N; }
    else if (MODE == 1) { A = g_O; B = Bm; lda = DMODEL; ldb = N; }
    else { A = g_P + (size_t)bh * T_SEQ * T_SEQ; B = g_V + (size_t)bh * T_SEQ * DH;
           lda = T_SEQ; ldb = DH; }

    // loaders
    int m_a = t >> 1,       kq_a = (t & 1) * 8;    // A: [m][k0+kq..+7]
    int k_b = t >> 4,       n_b  = (t & 15) * 8;   // B: [k0+k_b][n0+n_b..+7]
    int n_r = t >> 1,       kq_r = (t & 1) * 8;    // repack: column n_r, k kq_r..+7

    float d[2][8][4];
    #pragma unroll
    for (int mt = 0; mt < 2; mt++)
        #pragma unroll
        for (int nt = 0; nt < 8; nt++)
            #pragma unroll
            for (int q = 0; q < 4; q++) d[mt][nt][q] = 0.0f;

    float4 ra0, ra1, rb0, rb1;
    {
        const float* Ap = A + (size_t)(m0 + m_a) * lda + kq_a;
        const float* Bp = B + (size_t)k_b * ldb + n0 + n_b;
        ra0 = *(const float4*)Ap;       ra1 = *(const float4*)(Ap + 4);
        rb0 = *(const float4*)Bp;       rb1 = *(const float4*)(Bp + 4);
    }

    for (int k0 = 0; k0 < K; k0 += 16) {
        __syncthreads();
        // store A split-packed (k-pairs contiguous in row-major A)
        {
            float fa[8] = {ra0.x,ra0.y,ra0.z,ra0.w,ra1.x,ra1.y,ra1.z,ra1.w};
            unsigned h[4], l[4];
            #pragma unroll
            for (int j = 0; j < 4; j++) split_pack(fa[2*j], fa[2*j+1], h[j], l[j]);
            *(uint4*)&As_hi[m_a][kq_a >> 1] = make_uint4(h[0],h[1],h[2],h[3]);
            *(uint4*)&As_lo[m_a][kq_a >> 1] = make_uint4(l[0],l[1],l[2],l[3]);
            *(float4*)&Bf[k_b][n_b]     = rb0;
            *(float4*)&Bf[k_b][n_b + 4] = rb1;
        }
        __syncthreads();
        // repack B: [k][n] fp32 -> [n][k-pairs] split bf16
        {
            float fb[8];
            #pragma unroll
            for (int j = 0; j < 8; j++) fb[j] = Bf[kq_r + j][n_r];
            unsigned h[4], l[4];
            #pragma unroll
            for (int j = 0; j < 4; j++) split_pack(fb[2*j], fb[2*j+1], h[j], l[j]);
            *(uint4*)&Bs_hi[n_r][kq_r >> 1] = make_uint4(h[0],h[1],h[2],h[3]);
            *(uint4*)&Bs_lo[n_r][kq_r >> 1] = make_uint4(l[0],l[1],l[2],l[3]);
        }
        __syncthreads();

        if (k0 + 16 < K) {  // prefetch next panel
            const float* Ap = A + (size_t)(m0 + m_a) * lda + k0 + 16 + kq_a;
            const float* Bp = B + (size_t)(k0 + 16 + k_b) * ldb + n0 + n_b;
            ra0 = *(const float4*)Ap;   ra1 = *(const float4*)(Ap + 4);
            rb0 = *(const float4*)Bp;   rb1 = *(const float4*)(Bp + 4);
        }

        unsigned ah[2][4], al[2][4];
        #pragma unroll
        for (int mt = 0; mt < 2; mt++) {
            int rm = wm * 32 + mt * 16 + g;
            ah[mt][0] = As_hi[rm][tig];     ah[mt][1] = As_hi[rm + 8][tig];
            ah[mt][2] = As_hi[rm][tig + 4]; ah[mt][3] = As_hi[rm + 8][tig + 4];
            al[mt][0] = As_lo[rm][tig];     al[mt][1] = As_lo[rm + 8][tig];
            al[mt][2] = As_lo[rm][tig + 4]; al[mt][3] = As_lo[rm + 8][tig + 4];
        }
        #pragma unroll
        for (int nt = 0; nt < 8; nt++) {
            int rn = wn * 64 + nt * 8 + g;
            unsigned bh0 = Bs_hi[rn][tig], bh1 = Bs_hi[rn][tig + 4];
            unsigned bl0 = Bs_lo[rn][tig], bl1 = Bs_lo[rn][tig + 4];
            #pragma unroll
            for (int mt = 0; mt < 2; mt++) {
                mma_bf16(d[mt][nt], ah[mt], bh0, bh1);
                mma_bf16(d[mt][nt], ah[mt], bl0, bl1);
                mma_bf16(d[mt][nt], al[mt], bh0, bh1);
            }
        }
    }

    // epilogue
    #pragma unroll
    for (int mt = 0; mt < 2; mt++) {
        #pragma unroll
        for (int r = 0; r < 2; r++) {
            int m = m0 + wm * 32 + mt * 16 + g + r * 8;
            #pragma unroll
            for (int nt = 0; nt < 8; nt++) {
                int col = wn * 64 + nt * 8 + tig * 2;
                float v0 = d[mt][nt][r * 2 + 0];
                float v1 = d[mt][nt][r * 2 + 1];
                if (MODE == 2) {
                    float inv = g_Sinv[(size_t)bh * T_SEQ + m];
                    int b = bh >> 3, h = bh & 7;
                    float* dst = &g_O[(size_t)(b * T_SEQ + m) * DMODEL + h * DH + col];
                    dst[0] = v0 * inv; dst[1] = v1 * inv;
                } else {
                    v0 += bias[n0 + col]; v1 += bias[n0 + col + 1];
                    if (MODE == 0) {
                        int grp = n0 >> 7, part = grp >> 3, h = grp & 7;
                        float* dstb = (part == 0) ? g_Q : ((part == 1) ? g_K : g_V);
                        int bb = m >> 11, tt = m & 2047;
                        float* dst = &dstb[((size_t)(bb * NH + h) * T_SEQ + tt) * DH + (n0 & 127) + col];
                        dst[0] = v0; dst[1] = v1;
                    } else {
                        float* dst = &Cout[(size_t)m * N + n0 + col];
                        dst[0] = v0; dst[1] = v1;
                    }
                }
            }
        }
    }
}

// splat weights (unchanged)
__global__ void __launch_bounds__(256) weights_kernel(
    const float* __restrict__ centers, const float* __restrict__ lsc,
    const float* __restrict__ lam)
{
    __shared__ float c_sm[32][129];
    __shared__ float q_sm[8][128];

    int isK = blockIdx.y;
    int r0  = blockIdx.x * 8;
    int t = threadIdx.x, w = t >> 5, lane = t & 31;
    int h = (r0 >> 11) & 7;

    const float* cp = centers + h * NS * DH;
    for (int u = t; u < NS * DH; u += 256)
        c_sm[u >> 7][u & 127] = cp[u];

    const float* src = (isK ? g_K : g_Q) + (size_t)r0 * DH;
    #pragma unroll
    for (int u = 0; u < 4; u++)
        q_sm[w][lane + 32*u] = src[w * DH + lane + 32*u];
    __syncthreads();

    int s = lane;
    float scale = fast_exp(lsc[h * NS + s]);
    float inv = 1.0f / (scale + 1e-6f);
    float amp = isK ? 1.0f : fast_exp(lam[h * NS + s]);
    float coef = -0.5f * inv * inv;

    float d2 = 0.0f;
    #pragma unroll
    for (int k = 0; k < 128; k++) {
        float diff = q_sm[w][k] - c_sm[s][k];
        d2 = fmaf(diff, diff, d2);
    }
    (isK ? g_KW : g_QW)[(size_t)(r0 + w) * NS + s] = fast_exp(d2 * coef) * amp;
}

// logits + exp + row-sum; KW tiles staged in smem (coalesced LDG, conflict-free LDS.128)
__global__ void __launch_bounds__(256) logits_kernel(const float* __restrict__ temp)
{
    __shared__ __align__(16) float qa_sm[128][NS];
    __shared__ __align__(16) float kw_sm[128][36];

    int bh = blockIdx.y;
    int i0 = blockIdx.x * 128;
    int t = threadIdx.x, w = t >> 5, lane = t & 31;
    float invT = 1.0f / temp[0];

    const float* QWp = g_QW + ((size_t)bh * T_SEQ + i0) * NS;
    for (int u = t; u < 128 * NS; u += 256)
        qa_sm[u >> 5][u & 31] = QWp[u];

    const float* KWh = g_KW + (size_t)bh * T_SEQ * NS;
    float* Pw = g_P + ((size_t)bh * T_SEQ + i0 + w * 16) * T_SEQ;

    float sloc[16];
    #pragma unroll
    for (int i = 0; i < 16; i++) sloc[i] = 0.0f;

    for (int j0 = 0; j0 < T_SEQ; j0 += 128) {
        __syncthreads();
        for (int u = t; u < 128 * NS; u += 256)
            kw_sm[u >> 5][u & 31] = KWh[(size_t)j0 * NS + u];
        __syncthreads();

        #pragma unroll
        for (int jj = 0; jj < 4; jj++) {
            int j = jj * 32 + lane;
            float4 kw[8];
            #pragma unroll
            for (int q = 0; q < 8; q++) kw[q] = *(const float4*)&kw_sm[j][q * 4];
            #pragma unroll
            for (int i = 0; i < 16; i++) {
                const float4* qp = (const float4*)qa_sm[w * 16 + i];
                float acc = 0.0f;
                #pragma unroll
                for (int q = 0; q < 8; q++) {
                    float4 a4 = qp[q];
                    acc = fmaf(a4.x, kw[q].x, acc);
                    acc = fmaf(a4.y, kw[q].y, acc);
                    acc = fmaf(a4.z, kw[q].z, acc);
                    acc = fmaf(a4.w, kw[q].w, acc);
                }
                float e = fast_exp(acc * invT);
                sloc[i] += e;
                Pw[(size_t)i * T_SEQ + j0 + j] = e;
            }
        }
    }

    #pragma unroll
    for (int i = 0; i < 16; i++) {
        float sv = sloc[i];
        #pragma unroll
        for (int off = 16; off > 0; off >>= 1)
            sv += __shfl_xor_sync(0xffffffffu, sv, off);
        if (lane == 0)
            g_Sinv[(size_t)bh * T_SEQ + i0 + w * 16 + i] = 1.0f / sv;
    }
}

// bhij -> bijh transpose + normalize (unchanged)
__global__ void __launch_bounds__(256) transpose_kernel(float* __restrict__ attn)
{
    __shared__ float p_sm[512 * 9];

    int bi = blockIdx.x;
    int b = bi >> 11, i = bi & 2047;
    int t = threadIdx.x, w = t >> 5, lane = t & 31;

    const float* src = g_P + ((size_t)(b * NH + w) * T_SEQ + i) * T_SEQ;
    float inv = g_Sinv[(size_t)(b * NH + w) * T_SEQ + i];
    float* dst = attn + ((size_t)(b * T_SEQ + i)) * T_SEQ * NH;

    for (int c = 0; c < 4; c++) {
        #pragma unroll
        for (int r = 0; r < 16; r++) {
            int j = r * 32 + lane;
            p_sm[j * 9 + w] = src[c * 512 + j] * inv;
        }
        __syncthreads();
        #pragma unroll
        for (int r = 0; r < 16; r++) {
            int u = r * 256 + t;
            dst[c * 4096 + u] = p_sm[(u >> 3) * 9 + (u & 7)];
        }
        __syncthreads();
    }
}

extern "C" void kernel_launch(void* const* d_in, const int* in_sizes, int n_in,
                              void* d_out, int out_size)
{
    const float* x       = (const float*)d_in[0];
    const float* Wqkv    = (const float*)d_in[1];
    const float* bqkv    = (const float*)d_in[2];
    const float* Wout    = (const float*)d_in[3];
    const float* bout    = (const float*)d_in[4];
    const float* centers = (const float*)d_in[5];
    const float* lsc     = (const float*)d_in[6];
    const float* lam     = (const float*)d_in[7];
    const float* temp    = (const float*)d_in[8];

    float* out  = (float*)d_out;
    float* attn = out + (size_t)NB * T_SEQ * DMODEL;

    gemm_t_kernel<0><<<dim3(3 * DMODEL / 128, (NB * T_SEQ) / 128), 256>>>(
        x, Wqkv, bqkv, nullptr, 3 * DMODEL, DMODEL);

    weights_kernel<<<dim3((NB * NH * T_SEQ) / 8, 2), 256>>>(centers, lsc, lam);

    logits_kernel<<<dim3(T_SEQ / 128, NB * NH), 256>>>(temp);

    gemm_t_kernel<2><<<dim3(T_SEQ / 128, NB * NH), 256>>>(
        nullptr, nullptr, nullptr, nullptr, DH, T_SEQ);

    transpose_kernel<<<NB * T_SEQ, 256>>>(attn);

    gemm_t_kernel<1><<<dim3(DMODEL / 128, (NB * T_SEQ) / 128), 256>>>(
        nullptr, Wout, bout, out, DMODEL, DMODEL);
}

// round 5
// speedup vs baseline: 3.7654x; 3.7654x over previous
#include <cuda_runtime.h>
#include <cuda_bf16.h>
#include <cuda_fp16.h>

#define T_SEQ 2048
#define NB 2
#define NH 8
#define NS 32
#define DH 128
#define DMODEL 1024

__device__ float g_Q[NB*NH*T_SEQ*DH];
__device__ float g_K[NB*NH*T_SEQ*DH];
__device__ float g_V[NB*NH*T_SEQ*DH];
__device__ float g_QW[NB*NH*T_SEQ*NS];
__device__ float g_KW[NB*NH*T_SEQ*NS];
__device__ float g_O[NB*T_SEQ*DMODEL];
__device__ __half g_P[(size_t)NB*NH*T_SEQ*T_SEQ];   // unnormalized exp(logits), fp16, bhij
__device__ float g_Sinv[NB*NH*T_SEQ];

__device__ __forceinline__ float fast_exp(float x) {
    float t = x * 1.4426950408889634f;
    t = fmaxf(t, -126.0f);
    float fi = floorf(t);
    float f = t - fi;
    float p = 1.5403530e-4f;
    p = fmaf(p, f, 1.3333558e-3f);
    p = fmaf(p, f, 9.6181291e-3f);
    p = fmaf(p, f, 5.5504109e-2f);
    p = fmaf(p, f, 2.4022651e-1f);
    p = fmaf(p, f, 6.9314718e-1f);
    p = fmaf(p, f, 1.0f);
    return p * __int_as_float(((int)fi + 127) << 23);
}

// ---- bf16 split (for fp32-input GEMMs) ----
__device__ __forceinline__ void split_pack(float f0, float f1, unsigned& hi, unsigned& lo) {
    unsigned u0 = __float_as_uint(f0), u1 = __float_as_uint(f1);
    hi = __byte_perm(u0, u1, 0x7632);
    float l0 = f0 - __uint_as_float(u0 & 0xffff0000u);
    float l1 = f1 - __uint_as_float(u1 & 0xffff0000u);
    asm("cvt.rn.bf16x2.f32 %0, %1, %2;" : "=r"(lo) : "f"(l1), "f"(l0));
}
__device__ __forceinline__ void mma_bf16(float* d, const unsigned* a, unsigned b0, unsigned b1) {
    asm volatile(
        "mma.sync.aligned.m16n8k16.row.col.f32.bf16.bf16.f32 "
        "{%0,%1,%2,%3}, {%4,%5,%6,%7}, {%8,%9}, {%0,%1,%2,%3};"
        : "+f"(d[0]), "+f"(d[1]), "+f"(d[2]), "+f"(d[3])
        : "r"(a[0]), "r"(a[1]), "r"(a[2]), "r"(a[3]), "r"(b0), "r"(b1));
}

// ---- fp16 split (for logits / AV path) ----
__device__ __forceinline__ void split_pack_h(float f0, float f1, unsigned& hi, unsigned& lo) {
    __half2 h2 = __floats2half2_rn(f0, f1);     // low = f0
    hi = *reinterpret_cast<unsigned*>(&h2);
    float r0 = f0 - __low2float(h2);
    float r1 = f1 - __high2float(h2);
    __half2 l2 = __floats2half2_rn(r0, r1);
    lo = *reinterpret_cast<unsigned*>(&l2);
}
__device__ __forceinline__ void mma_f16(float* d, const unsigned* a, unsigned b0, unsigned b1) {
    asm volatile(
        "mma.sync.aligned.m16n8k16.row.col.f32.f16.f16.f32 "
        "{%0,%1,%2,%3}, {%4,%5,%6,%7}, {%8,%9}, {%0,%1,%2,%3};"
        : "+f"(d[0]), "+f"(d[1]), "+f"(d[2]), "+f"(d[3])
        : "r"(a[0]), "r"(a[1]), "r"(a[2]), "r"(a[3]), "r"(b0), "r"(b1));
}

// Tensor GEMM (bf16 3-term split), block 128x128, K-panel 16, 8 warps.
// MODE 0: x@Wqkv+bqkv -> scatter g_Q/g_K/g_V.  MODE 1: g_O@Wout+bout -> Cout.
template<int MODE>
__global__ void __launch_bounds__(256, 2) gemm_t_kernel(
    const float* __restrict__ Ain, const float* __restrict__ Bm,
    const float* __restrict__ bias, float* __restrict__ Cout,
    int N, int K)
{
    __shared__ unsigned As_hi[128][12], As_lo[128][12];
    __shared__ unsigned Bs_hi[128][12], Bs_lo[128][12];
    __shared__ float Bf[16][132];

    int t = threadIdx.x, warp = t >> 5, lane = t & 31;
    int g = lane >> 2, tig = lane & 3;
    int wm = warp >> 1, wn = warp & 1;

    int n0 = blockIdx.x * 128, m0 = blockIdx.y * 128;
    const float* A = (MODE == 1) ? (const float*)g_O : Ain;
    const float* B = Bm;
    int lda = DMODEL, ldb = N;

    int m_a = t >> 1, kq_a = (t & 1) * 8;
    int k_b = t >> 4, n_b = (t & 15) * 8;
    int n_r = t >> 1, kq_r = (t & 1) * 8;

    float d[2][8][4];
    #pragma unroll
    for (int mt = 0; mt < 2; mt++)
        #pragma unroll
        for (int nt = 0; nt < 8; nt++)
            #pragma unroll
            for (int q = 0; q < 4; q++) d[mt][nt][q] = 0.0f;

    float4 ra0, ra1, rb0, rb1;
    {
        const float* Ap = A + (size_t)(m0 + m_a) * lda + kq_a;
        const float* Bp = B + (size_t)k_b * ldb + n0 + n_b;
        ra0 = *(const float4*)Ap; ra1 = *(const float4*)(Ap + 4);
        rb0 = *(const float4*)Bp; rb1 = *(const float4*)(Bp + 4);
    }

    for (int k0 = 0; k0 < K; k0 += 16) {
        __syncthreads();
        {
            float fa[8] = {ra0.x,ra0.y,ra0.z,ra0.w,ra1.x,ra1.y,ra1.z,ra1.w};
            unsigned h[4], l[4];
            #pragma unroll
            for (int j = 0; j < 4; j++) split_pack(fa[2*j], fa[2*j+1], h[j], l[j]);
            *(uint4*)&As_hi[m_a][kq_a >> 1] = make_uint4(h[0],h[1],h[2],h[3]);
            *(uint4*)&As_lo[m_a][kq_a >> 1] = make_uint4(l[0],l[1],l[2],l[3]);
            *(float4*)&Bf[k_b][n_b]     = rb0;
            *(float4*)&Bf[k_b][n_b + 4] = rb1;
        }
        __syncthreads();
        {
            float fb[8];
            #pragma unroll
            for (int j = 0; j < 8; j++) fb[j] = Bf[kq_r + j][n_r];
            unsigned h[4], l[4];
            #pragma unroll
            for (int j = 0; j < 4; j++) split_pack(fb[2*j], fb[2*j+1], h[j], l[j]);
            *(uint4*)&Bs_hi[n_r][kq_r >> 1] = make_uint4(h[0],h[1],h[2],h[3]);
            *(uint4*)&Bs_lo[n_r][kq_r >> 1] = make_uint4(l[0],l[1],l[2],l[3]);
        }
        __syncthreads();

        if (k0 + 16 < K) {
            const float* Ap = A + (size_t)(m0 + m_a) * lda + k0 + 16 + kq_a;
            const float* Bp = B + (size_t)(k0 + 16 + k_b) * ldb + n0 + n_b;
            ra0 = *(const float4*)Ap; ra1 = *(const float4*)(Ap + 4);
            rb0 = *(const float4*)Bp; rb1 = *(const float4*)(Bp + 4);
        }

        unsigned ah[2][4], al[2][4];
        #pragma unroll
        for (int mt = 0; mt < 2; mt++) {
            int rm = wm * 32 + mt * 16 + g;
            ah[mt][0] = As_hi[rm][tig];     ah[mt][1] = As_hi[rm + 8][tig];
            ah[mt][2] = As_hi[rm][tig + 4]; ah[mt][3] = As_hi[rm + 8][tig + 4];
            al[mt][0] = As_lo[rm][tig];     al[mt][1] = As_lo[rm + 8][tig];
            al[mt][2] = As_lo[rm][tig + 4]; al[mt][3] = As_lo[rm + 8][tig + 4];
        }
        #pragma unroll
        for (int nt = 0; nt < 8; nt++) {
            int rn = wn * 64 + nt * 8 + g;
            unsigned bh0 = Bs_hi[rn][tig], bh1 = Bs_hi[rn][tig + 4];
            unsigned bl0 = Bs_lo[rn][tig], bl1 = Bs_lo[rn][tig + 4];
            #pragma unroll
            for (int mt = 0; mt < 2; mt++) {
                mma_bf16(d[mt][nt], ah[mt], bh0, bh1);
                mma_bf16(d[mt][nt], ah[mt], bl0, bl1);
                mma_bf16(d[mt][nt], al[mt], bh0, bh1);
            }
        }
    }

    #pragma unroll
    for (int mt = 0; mt < 2; mt++) {
        #pragma unroll
        for (int r = 0; r < 2; r++) {
            int m = m0 + wm * 32 + mt * 16 + g + r * 8;
            #pragma unroll
            for (int nt = 0; nt < 8; nt++) {
                int col = wn * 64 + nt * 8 + tig * 2;
                float v0 = d[mt][nt][r * 2 + 0] + bias[n0 + col];
                float v1 = d[mt][nt][r * 2 + 1] + bias[n0 + col + 1];
                if (MODE == 0) {
                    int grp = n0 >> 7, part = grp >> 3, h = grp & 7;
                    float* dstb = (part == 0) ? g_Q : ((part == 1) ? g_K : g_V);
                    int bb = m >> 11, tt = m & 2047;
                    float* dst = &dstb[((size_t)(bb * NH + h) * T_SEQ + tt) * DH + col];
                    dst[0] = v0; dst[1] = v1;
                } else {
                    float* dst = &Cout[(size_t)m * N + n0 + col];
                    dst[0] = v0; dst[1] = v1;
                }
            }
        }
    }
}

// splat weights; isK passed so it can be 2 launches (profiler position control)
__global__ void __launch_bounds__(256) weights_kernel(
    const float* __restrict__ centers, const float* __restrict__ lsc,
    const float* __restrict__ lam, int isK)
{
    __shared__ float c_sm[32][129];
    __shared__ float q_sm[8][128];

    int r0 = blockIdx.x * 8;
    int t = threadIdx.x, w = t >> 5, lane = t & 31;
    int h = (r0 >> 11) & 7;

    const float* cp = centers + h * NS * DH;
    for (int u = t; u < NS * DH; u += 256)
        c_sm[u >> 7][u & 127] = cp[u];

    const float* src = (isK ? g_K : g_Q) + (size_t)r0 * DH;
    #pragma unroll
    for (int u = 0; u < 4; u++)
        q_sm[w][lane + 32*u] = src[w * DH + lane + 32*u];
    __syncthreads();

    int s = lane;
    float scale = fast_exp(lsc[h * NS + s]);
    float inv = 1.0f / (scale + 1e-6f);
    float amp = isK ? 1.0f : fast_exp(lam[h * NS + s]);
    float coef = -0.5f * inv * inv;

    float d2 = 0.0f;
    #pragma unroll
    for (int k = 0; k < 128; k++) {
        float diff = q_sm[w][k] - c_sm[s][k];
        d2 = fmaf(diff, diff, d2);
    }
    (isK ? g_KW : g_QW)[(size_t)(r0 + w) * NS + s] = fast_exp(d2 * coef) * amp;
}

// logits on tensor cores (fp16 3-term split), K=32. Block = (bh, 64 i-rows).
// Warp tile 16i x 64j, j-chunks of 128. Writes P fp16 + row-sum inverses.
__global__ void __launch_bounds__(256) logits_t_kernel(const float* __restrict__ temp)
{
    __shared__ unsigned Qs_hi[64][20], Qs_lo[64][20];
    __shared__ unsigned Ks_hi[128][20], Ks_lo[128][20];
    __shared__ __half  Pst[64][136];
    __shared__ float   sums_sm[2][64];

    int bh = blockIdx.y;
    int i0 = blockIdx.x * 64;
    int t = threadIdx.x, warp = t >> 5, lane = t & 31;
    int g = lane >> 2, tig = lane & 3;
    int wm = warp >> 1, wn = warp & 1;
    float invT = 1.0f / temp[0];

    {   // QW tile [64][32] split-fp16
        int row = t >> 2, s0 = (t & 3) * 8;
        const float* p = g_QW + ((size_t)bh * T_SEQ + i0 + row) * NS + s0;
        float4 f0 = *(const float4*)p, f1 = *(const float4*)(p + 4);
        float fa[8] = {f0.x,f0.y,f0.z,f0.w,f1.x,f1.y,f1.z,f1.w};
        unsigned h[4], l[4];
        #pragma unroll
        for (int j = 0; j < 4; j++) split_pack_h(fa[2*j], fa[2*j+1], h[j], l[j]);
        *(uint4*)&Qs_hi[row][s0 >> 1] = make_uint4(h[0],h[1],h[2],h[3]);
        *(uint4*)&Qs_lo[row][s0 >> 1] = make_uint4(l[0],l[1],l[2],l[3]);
    }

    const float* KWb = g_KW + (size_t)bh * T_SEQ * NS;
    __half* Pb = g_P + ((size_t)bh * T_SEQ + i0) * T_SEQ;

    float sl0 = 0.0f, sl1 = 0.0f;

    for (int j0 = 0; j0 < T_SEQ; j0 += 128) {
        __syncthreads();
        #pragma unroll
        for (int rr = 0; rr < 2; rr++) {   // KW chunk [128][32]
            int row = (t >> 2) + rr * 64, s0 = (t & 3) * 8;
            const float* p = KWb + (size_t)(j0 + row) * NS + s0;
            float4 f0 = *(const float4*)p, f1 = *(const float4*)(p + 4);
            float fb[8] = {f0.x,f0.y,f0.z,f0.w,f1.x,f1.y,f1.z,f1.w};
            unsigned h[4], l[4];
            #pragma unroll
            for (int j = 0; j < 4; j++) split_pack_h(fb[2*j], fb[2*j+1], h[j], l[j]);
            *(uint4*)&Ks_hi[row][s0 >> 1] = make_uint4(h[0],h[1],h[2],h[3]);
            *(uint4*)&Ks_lo[row][s0 >> 1] = make_uint4(l[0],l[1],l[2],l[3]);
        }
        __syncthreads();

        float d[8][4];
        #pragma unroll
        for (int nt = 0; nt < 8; nt++)
            #pragma unroll
            for (int q = 0; q < 4; q++) d[nt][q] = 0.0f;

        #pragma unroll
        for (int p2 = 0; p2 < 2; p2++) {
            int rm = wm * 16 + g;
            unsigned ah[4], al[4];
            ah[0] = Qs_hi[rm][p2*8 + tig];     ah[1] = Qs_hi[rm + 8][p2*8 + tig];
            ah[2] = Qs_hi[rm][p2*8 + tig + 4]; ah[3] = Qs_hi[rm + 8][p2*8 + tig + 4];
            al[0] = Qs_lo[rm][p2*8 + tig];     al[1] = Qs_lo[rm + 8][p2*8 + tig];
            al[2] = Qs_lo[rm][p2*8 + tig + 4]; al[3] = Qs_lo[rm + 8][p2*8 + tig + 4];
            #pragma unroll
            for (int nt = 0; nt < 8; nt++) {
                int rn = wn * 64 + nt * 8 + g;
                unsigned kh0 = Ks_hi[rn][p2*8 + tig], kh1 = Ks_hi[rn][p2*8 + tig + 4];
                unsigned kl0 = Ks_lo[rn][p2*8 + tig], kl1 = Ks_lo[rn][p2*8 + tig + 4];
                mma_f16(d[nt], ah, kh0, kh1);
                mma_f16(d[nt], ah, kl0, kl1);
                mma_f16(d[nt], al, kh0, kh1);
            }
        }

        #pragma unroll
        for (int nt = 0; nt < 8; nt++) {
            float e0 = fast_exp(d[nt][0] * invT);
            float e1 = fast_exp(d[nt][1] * invT);
            float e2 = fast_exp(d[nt][2] * invT);
            float e3 = fast_exp(d[nt][3] * invT);
            sl0 += e0 + e1;  sl1 += e2 + e3;
            int r0 = wm * 16 + g, c = wn * 64 + nt * 8 + tig * 2;
            *(__half2*)&Pst[r0][c]     = __floats2half2_rn(e0, e1);
            *(__half2*)&Pst[r0 + 8][c] = __floats2half2_rn(e2, e3);
        }
        __syncthreads();

        #pragma unroll
        for (int r = 0; r < 8; r++) {   // coalesced fp16 store, warp -> 8 rows
            int row = warp * 8 + r;
            uint2 v = *(uint2*)&Pst[row][lane * 4];
            *(uint2*)&Pb[(size_t)row * T_SEQ + j0 + lane * 4] = v;
        }
    }

    sl0 += __shfl_xor_sync(0xffffffffu, sl0, 1);
    sl0 += __shfl_xor_sync(0xffffffffu, sl0, 2);
    sl1 += __shfl_xor_sync(0xffffffffu, sl1, 1);
    sl1 += __shfl_xor_sync(0xffffffffu, sl1, 2);
    if (tig == 0) {
        sums_sm[wn][wm * 16 + g]     = sl0;
        sums_sm[wn][wm * 16 + g + 8] = sl1;
    }
    __syncthreads();
    if (t < 64)
        g_Sinv[(size_t)bh * T_SEQ + i0 + t] = 1.0f / (sums_sm[0][t] + sums_sm[1][t]);
}

// AV: O = (P@V)*Sinv, P fp16 (A direct), V fp32 (2-term fp16 split). Per-bh batch.
__global__ void __launch_bounds__(256, 2) av_t_kernel()
{
    __shared__ unsigned As[128][12];
    __shared__ unsigned Bs_hi[128][12], Bs_lo[128][12];
    __shared__ float Bf[16][132];

    int t = threadIdx.x, warp = t >> 5, lane = t & 31;
    int g = lane >> 2, tig = lane & 3;
    int wm = warp >> 1, wn = warp & 1;

    int bh = blockIdx.y;
    int m0 = blockIdx.x * 128;
    const __half* A = g_P + (size_t)bh * T_SEQ * T_SEQ;
    const float* B = g_V + (size_t)bh * T_SEQ * DH;

    int m_a = t >> 1, ka = (t & 1) * 8;     // 8 halves per thread
    int k_b = t >> 4, n_b = (t & 15) * 8;
    int n_r = t >> 1, kq_r = (t & 1) * 8;

    float d[2][8][4];
    #pragma unroll
    for (int mt = 0; mt < 2; mt++)
        #pragma unroll
        for (int nt = 0; nt < 8; nt++)
            #pragma unroll
            for (int q = 0; q < 4; q++) d[mt][nt][q] = 0.0f;

    uint4 raw; float4 rb0, rb1;
    raw = *(const uint4*)&A[(size_t)(m0 + m_a) * T_SEQ + ka];
    {
        const float* Bp = B + (size_t)k_b * DH + n_b;
        rb0 = *(const float4*)Bp; rb1 = *(const float4*)(Bp + 4);
    }

    for (int k0 = 0; k0 < T_SEQ; k0 += 16) {
        __syncthreads();
        *(uint4*)&As[m_a][(t & 1) * 4] = raw;
        *(float4*)&Bf[k_b][n_b]     = rb0;
        *(float4*)&Bf[k_b][n_b + 4] = rb1;
        __syncthreads();
        {
            float fb[8];
            #pragma unroll
            for (int j = 0; j < 8; j++) fb[j] = Bf[kq_r + j][n_r];
            unsigned h[4], l[4];
            #pragma unroll
            for (int j = 0; j < 4; j++) split_pack_h(fb[2*j], fb[2*j+1], h[j], l[j]);
            *(uint4*)&Bs_hi[n_r][kq_r >> 1] = make_uint4(h[0],h[1],h[2],h[3]);
            *(uint4*)&Bs_lo[n_r][kq_r >> 1] = make_uint4(l[0],l[1],l[2],l[3]);
        }
        __syncthreads();

        if (k0 + 16 < T_SEQ) {
            raw = *(const uint4*)&A[(size_t)(m0 + m_a) * T_SEQ + k0 + 16 + ka];
            const float* Bp = B + (size_t)(k0 + 16 + k_b) * DH + n_b;
            rb0 = *(const float4*)Bp; rb1 = *(const float4*)(Bp + 4);
        }

        unsigned a[2][4];
        #pragma unroll
        for (int mt = 0; mt < 2; mt++) {
            int rm = wm * 32 + mt * 16 + g;
            a[mt][0] = As[rm][tig];     a[mt][1] = As[rm + 8][tig];
            a[mt][2] = As[rm][tig + 4]; a[mt][3] = As[rm + 8][tig + 4];
        }
        #pragma unroll
        for (int nt = 0; nt < 8; nt++) {
            int rn = wn * 64 + nt * 8 + g;
            unsigned bh0 = Bs_hi[rn][tig], bh1 = Bs_hi[rn][tig + 4];
            unsigned bl0 = Bs_lo[rn][tig], bl1 = Bs_lo[rn][tig + 4];
            #pragma unroll
            for (int mt = 0; mt < 2; mt++) {
                mma_f16(d[mt][nt], a[mt], bh0, bh1);
                mma_f16(d[mt][nt], a[mt], bl0, bl1);
            }
        }
    }

    int b = bh >> 3, h = bh & 7;
    #pragma unroll
    for (int mt = 0; mt < 2; mt++) {
        #pragma unroll
        for (int r = 0; r < 2; r++) {
            int m = m0 + wm * 32 + mt * 16 + g + r * 8;
            float inv = g_Sinv[(size_t)bh * T_SEQ + m];
            #pragma unroll
            for (int nt = 0; nt < 8; nt++) {
                int col = wn * 64 + nt * 8 + tig * 2;
                float* dst = &g_O[(size_t)(b * T_SEQ + m) * DMODEL + h * DH + col];
                dst[0] = d[mt][nt][r*2 + 0] * inv;
                dst[1] = d[mt][nt][r*2 + 1] * inv;
            }
        }
    }
}

// bhij(fp16) -> bijh(fp32) transpose + normalize
__global__ void __launch_bounds__(256) transpose_kernel(float* __restrict__ attn)
{
    __shared__ float p_sm[512 * 9];

    int bi = blockIdx.x;
    int b = bi >> 11, i = bi & 2047;
    int t = threadIdx.x, w = t >> 5, lane = t & 31;

    const __half* src = g_P + ((size_t)(b * NH + w) * T_SEQ + i) * T_SEQ;
    float inv = g_Sinv[(size_t)(b * NH + w) * T_SEQ + i];
    float* dst = attn + ((size_t)(b * T_SEQ + i)) * T_SEQ * NH;

    for (int c = 0; c < 4; c++) {
        #pragma unroll
        for (int r = 0; r < 8; r++) {
            int u = r * 32 + lane;              // half2 index within chunk
            __half2 v = *(const __half2*)&src[c * 512 + u * 2];
            float2 f = __half22float2(v);
            p_sm[(2*u)     * 9 + w] = f.x * inv;
            p_sm[(2*u + 1) * 9 + w] = f.y * inv;
        }
        __syncthreads();
        #pragma unroll
        for (int r = 0; r < 16; r++) {
            int u = r * 256 + t;
            dst[c * 4096 + u] = p_sm[(u >> 3) * 9 + (u & 7)];
        }
        __syncthreads();
    }
}

extern "C" void kernel_launch(void* const* d_in, const int* in_sizes, int n_in,
                              void* d_out, int out_size)
{
    const float* x       = (const float*)d_in[0];
    const float* Wqkv    = (const float*)d_in[1];
    const float* bqkv    = (const float*)d_in[2];
    const float* Wout    = (const float*)d_in[3];
    const float* bout    = (const float*)d_in[4];
    const float* centers = (const float*)d_in[5];
    const float* lsc     = (const float*)d_in[6];
    const float* lam     = (const float*)d_in[7];
    const float* temp    = (const float*)d_in[8];

    float* out  = (float*)d_out;
    float* attn = out + (size_t)NB * T_SEQ * DMODEL;

    gemm_t_kernel<0><<<dim3(3 * DMODEL / 128, (NB * T_SEQ) / 128), 256>>>(
        x, Wqkv, bqkv, nullptr, 3 * DMODEL, DMODEL);                         // 1

    weights_kernel<<<(NB * NH * T_SEQ) / 8, 256>>>(centers, lsc, lam, 0);    // 2
    weights_kernel<<<(NB * NH * T_SEQ) / 8, 256>>>(centers, lsc, lam, 1);    // 3

    logits_t_kernel<<<dim3(T_SEQ / 64, NB * NH), 256>>>(temp);               // 4 <- profiled

    av_t_kernel<<<dim3(T_SEQ / 128, NB * NH), 256>>>();                      // 5

    transpose_kernel<<<NB * T_SEQ, 256>>>(attn);                             // 6

    gemm_t_kernel<1><<<dim3(DMODEL / 128, (NB * T_SEQ) / 128), 256>>>(
        nullptr, Wout, bout, out, DMODEL, DMODEL);                           // 7
}

// round 6
// speedup vs baseline: 4.5367x; 1.2048x over previous
#include <cuda_runtime.h>
#include <cuda_bf16.h>
#include <cuda_fp16.h>

#define T_SEQ 2048
#define NB 2
#define NH 8
#define NS 32
#define DH 128
#define DMODEL 1024

__device__ float g_Q[NB*NH*T_SEQ*DH];
__device__ float g_K[NB*NH*T_SEQ*DH];
__device__ float g_V[NB*NH*T_SEQ*DH];
__device__ float g_QW[NB*NH*T_SEQ*NS];
__device__ float g_KW[NB*NH*T_SEQ*NS];
__device__ float g_O[NB*T_SEQ*DMODEL];
__device__ __half g_P[(size_t)NB*NH*T_SEQ*T_SEQ];
__device__ float g_Sinv[NB*NH*T_SEQ];

__device__ __forceinline__ float fast_exp(float x) {
    float t = x * 1.4426950408889634f;
    t = fmaxf(t, -126.0f);
    float fi = floorf(t);
    float f = t - fi;
    float p = 1.5403530e-4f;
    p = fmaf(p, f, 1.3333558e-3f);
    p = fmaf(p, f, 9.6181291e-3f);
    p = fmaf(p, f, 5.5504109e-2f);
    p = fmaf(p, f, 2.4022651e-1f);
    p = fmaf(p, f, 6.9314718e-1f);
    p = fmaf(p, f, 1.0f);
    return p * __int_as_float(((int)fi + 127) << 23);
}

__device__ __forceinline__ void split_pack(float f0, float f1, unsigned& hi, unsigned& lo) {
    unsigned u0 = __float_as_uint(f0), u1 = __float_as_uint(f1);
    hi = __byte_perm(u0, u1, 0x7632);
    float l0 = f0 - __uint_as_float(u0 & 0xffff0000u);
    float l1 = f1 - __uint_as_float(u1 & 0xffff0000u);
    asm("cvt.rn.bf16x2.f32 %0, %1, %2;" : "=r"(lo) : "f"(l1), "f"(l0));
}
__device__ __forceinline__ void mma_bf16(float* d, const unsigned* a, unsigned b0, unsigned b1) {
    asm volatile(
        "mma.sync.aligned.m16n8k16.row.col.f32.bf16.bf16.f32 "
        "{%0,%1,%2,%3}, {%4,%5,%6,%7}, {%8,%9}, {%0,%1,%2,%3};"
        : "+f"(d[0]), "+f"(d[1]), "+f"(d[2]), "+f"(d[3])
        : "r"(a[0]), "r"(a[1]), "r"(a[2]), "r"(a[3]), "r"(b0), "r"(b1));
}
__device__ __forceinline__ void split_pack_h(float f0, float f1, unsigned& hi, unsigned& lo) {
    __half2 h2 = __floats2half2_rn(f0, f1);
    hi = *reinterpret_cast<unsigned*>(&h2);
    float r0 = f0 - __low2float(h2);
    float r1 = f1 - __high2float(h2);
    __half2 l2 = __floats2half2_rn(r0, r1);
    lo = *reinterpret_cast<unsigned*>(&l2);
}
__device__ __forceinline__ void mma_f16(float* d, const unsigned* a, unsigned b0, unsigned b1) {
    asm volatile(
        "mma.sync.aligned.m16n8k16.row.col.f32.f16.f16.f32 "
        "{%0,%1,%2,%3}, {%4,%5,%6,%7}, {%8,%9}, {%0,%1,%2,%3};"
        : "+f"(d[0]), "+f"(d[1]), "+f"(d[2]), "+f"(d[3])
        : "r"(a[0]), "r"(a[1]), "r"(a[2]), "r"(a[3]), "r"(b0), "r"(b1));
}

// Tensor GEMM v2 (bf16 3-term split): block 128x128, K-panel 32, 2 syncs/panel,
// direct strided B load (no staging/repack). 8 warps, warp tile 32x64.
// MODE 0: x@Wqkv+bqkv -> scatter g_Q/g_K/g_V.  MODE 1: g_O@Wout+bout -> Cout.
template<int MODE>
__global__ void __launch_bounds__(256, 2) gemm_t_kernel(
    const float* __restrict__ Ain, const float* __restrict__ Bm,
    const float* __restrict__ bias, float* __restrict__ Cout,
    int N, int K)
{
    __shared__ unsigned As_hi[128][20], As_lo[128][20];   // cols 0..15 = 16 k-pairs
    __shared__ unsigned Bs_hi[128][20], Bs_lo[128][20];

    int t = threadIdx.x, warp = t >> 5, lane = t & 31;
    int g = lane >> 2, tig = lane & 3;
    int wm = warp >> 1, wn = warp & 1;

    int n0 = blockIdx.x * 128, m0 = blockIdx.y * 128;
    const float* A = (MODE == 1) ? (const float*)g_O : Ain;
    const float* B = Bm;
    const int lda = DMODEL, ldb = N;

    int m_a = t >> 1, ca = (t & 1) * 16;      // A: row m_a, 16 floats at col ca
    int n_bb = t & 127, kh = (t >> 7) * 16;   // B: col n_bb, 16 k rows at kh

    float d[2][8][4];
    #pragma unroll
    for (int mt = 0; mt < 2; mt++)
        #pragma unroll
        for (int nt = 0; nt < 8; nt++)
            #pragma unroll
            for (int q = 0; q < 4; q++) d[mt][nt][q] = 0.0f;

    float a_r[16], b_r[16];
    {
        const float* Ap = A + (size_t)(m0 + m_a) * lda + ca;
        #pragma unroll
        for (int j = 0; j < 4; j++) *(float4*)&a_r[j*4] = *(const float4*)(Ap + j*4);
        const float* Bp = B + (size_t)kh * ldb + n0 + n_bb;
        #pragma unroll
        for (int j = 0; j < 16; j++) b_r[j] = Bp[(size_t)j * ldb];
    }

    for (int k0 = 0; k0 < K; k0 += 32) {
        __syncthreads();
        {
            unsigned h0[4], l0[4], h1[4], l1[4];
            #pragma unroll
            for (int j = 0; j < 4; j++) split_pack(a_r[2*j],   a_r[2*j+1],   h0[j], l0[j]);
            #pragma unroll
            for (int j = 0; j < 4; j++) split_pack(a_r[8+2*j], a_r[8+2*j+1], h1[j], l1[j]);
            *(uint4*)&As_hi[m_a][(ca>>1)]     = make_uint4(h0[0],h0[1],h0[2],h0[3]);
            *(uint4*)&As_hi[m_a][(ca>>1) + 4] = make_uint4(h1[0],h1[1],h1[2],h1[3]);
            *(uint4*)&As_lo[m_a][(ca>>1)]     = make_uint4(l0[0],l0[1],l0[2],l0[3]);
            *(uint4*)&As_lo[m_a][(ca>>1) + 4] = make_uint4(l1[0],l1[1],l1[2],l1[3]);

            #pragma unroll
            for (int j = 0; j < 4; j++) split_pack(b_r[2*j],   b_r[2*j+1],   h0[j], l0[j]);
            #pragma unroll
            for (int j = 0; j < 4; j++) split_pack(b_r[8+2*j], b_r[8+2*j+1], h1[j], l1[j]);
            *(uint4*)&Bs_hi[n_bb][(kh>>1)]     = make_uint4(h0[0],h0[1],h0[2],h0[3]);
            *(uint4*)&Bs_hi[n_bb][(kh>>1) + 4] = make_uint4(h1[0],h1[1],h1[2],h1[3]);
            *(uint4*)&Bs_lo[n_bb][(kh>>1)]     = make_uint4(l0[0],l0[1],l0[2],l0[3]);
            *(uint4*)&Bs_lo[n_bb][(kh>>1) + 4] = make_uint4(l1[0],l1[1],l1[2],l1[3]);
        }
        __syncthreads();

        if (k0 + 32 < K) {
            const float* Ap = A + (size_t)(m0 + m_a) * lda + k0 + 32 + ca;
            #pragma unroll
            for (int j = 0; j < 4; j++) *(float4*)&a_r[j*4] = *(const float4*)(Ap + j*4);
            const float* Bp = B + (size_t)(k0 + 32 + kh) * ldb + n0 + n_bb;
            #pragma unroll
            for (int j = 0; j < 16; j++) b_r[j] = Bp[(size_t)j * ldb];
        }

        #pragma unroll
        for (int half = 0; half < 2; half++) {
            int base = half * 8;
            unsigned ah[2][4], al[2][4];
            #pragma unroll
            for (int mt = 0; mt < 2; mt++) {
                int rm = wm * 32 + mt * 16 + g;
                ah[mt][0] = As_hi[rm][base + tig];     ah[mt][1] = As_hi[rm + 8][base + tig];
                ah[mt][2] = As_hi[rm][base + tig + 4]; ah[mt][3] = As_hi[rm + 8][base + tig + 4];
                al[mt][0] = As_lo[rm][base + tig];     al[mt][1] = As_lo[rm + 8][base + tig];
                al[mt][2] = As_lo[rm][base + tig + 4]; al[mt][3] = As_lo[rm + 8][base + tig + 4];
            }
            #pragma unroll
            for (int nt = 0; nt < 8; nt++) {
                int rn = wn * 64 + nt * 8 + g;
                unsigned bh0 = Bs_hi[rn][base + tig], bh1 = Bs_hi[rn][base + tig + 4];
                unsigned bl0 = Bs_lo[rn][base + tig], bl1 = Bs_lo[rn][base + tig + 4];
                #pragma unroll
                for (int mt = 0; mt < 2; mt++) {
                    mma_bf16(d[mt][nt], ah[mt], bh0, bh1);
                    mma_bf16(d[mt][nt], ah[mt], bl0, bl1);
                    mma_bf16(d[mt][nt], al[mt], bh0, bh1);
                }
            }
        }
    }

    #pragma unroll
    for (int mt = 0; mt < 2; mt++) {
        #pragma unroll
        for (int r = 0; r < 2; r++) {
            int m = m0 + wm * 32 + mt * 16 + g + r * 8;
            #pragma unroll
            for (int nt = 0; nt < 8; nt++) {
                int col = wn * 64 + nt * 8 + tig * 2;
                float v0 = d[mt][nt][r * 2 + 0] + bias[n0 + col];
                float v1 = d[mt][nt][r * 2 + 1] + bias[n0 + col + 1];
                if (MODE == 0) {
                    int grp = n0 >> 7, part = grp >> 3, h = grp & 7;
                    float* dstb = (part == 0) ? g_Q : ((part == 1) ? g_K : g_V);
                    int bb = m >> 11, tt = m & 2047;
                    float* dst = &dstb[((size_t)(bb * NH + h) * T_SEQ + tt) * DH + col];
                    dst[0] = v0; dst[1] = v1;
                } else {
                    float* dst = &Cout[(size_t)m * N + n0 + col];
                    dst[0] = v0; dst[1] = v1;
                }
            }
        }
    }
}

// splat weights, isK = blockIdx.y
__global__ void __launch_bounds__(256) weights_kernel(
    const float* __restrict__ centers, const float* __restrict__ lsc,
    const float* __restrict__ lam)
{
    __shared__ float c_sm[32][129];
    __shared__ float q_sm[8][128];

    int isK = blockIdx.y;
    int r0 = blockIdx.x * 8;
    int t = threadIdx.x, w = t >> 5, lane = t & 31;
    int h = (r0 >> 11) & 7;

    const float* cp = centers + h * NS * DH;
    for (int u = t; u < NS * DH; u += 256)
        c_sm[u >> 7][u & 127] = cp[u];

    const float* src = (isK ? g_K : g_Q) + (size_t)r0 * DH;
    #pragma unroll
    for (int u = 0; u < 4; u++)
        q_sm[w][lane + 32*u] = src[w * DH + lane + 32*u];
    __syncthreads();

    int s = lane;
    float scale = fast_exp(lsc[h * NS + s]);
    float inv = 1.0f / (scale + 1e-6f);
    float amp = isK ? 1.0f : fast_exp(lam[h * NS + s]);
    float coef = -0.5f * inv * inv;

    float d2 = 0.0f;
    #pragma unroll
    for (int k = 0; k < 128; k++) {
        float diff = q_sm[w][k] - c_sm[s][k];
        d2 = fmaf(diff, diff, d2);
    }
    (isK ? g_KW : g_QW)[(size_t)(r0 + w) * NS + s] = fast_exp(d2 * coef) * amp;
}

// logits on tensor cores (fp16 3-term split), unchanged from R4 (98.6us)
__global__ void __launch_bounds__(256) logits_t_kernel(const float* __restrict__ temp)
{
    __shared__ unsigned Qs_hi[64][20], Qs_lo[64][20];
    __shared__ unsigned Ks_hi[128][20], Ks_lo[128][20];
    __shared__ __half  Pst[64][136];
    __shared__ float   sums_sm[2][64];

    int bh = blockIdx.y;
    int i0 = blockIdx.x * 64;
    int t = threadIdx.x, warp = t >> 5, lane = t & 31;
    int g = lane >> 2, tig = lane & 3;
    int wm = warp >> 1, wn = warp & 1;
    float invT = 1.0f / temp[0];

    {
        int row = t >> 2, s0 = (t & 3) * 8;
        const float* p = g_QW + ((size_t)bh * T_SEQ + i0 + row) * NS + s0;
        float4 f0 = *(const float4*)p, f1 = *(const float4*)(p + 4);
        float fa[8] = {f0.x,f0.y,f0.z,f0.w,f1.x,f1.y,f1.z,f1.w};
        unsigned h[4], l[4];
        #pragma unroll
        for (int j = 0; j < 4; j++) split_pack_h(fa[2*j], fa[2*j+1], h[j], l[j]);
        *(uint4*)&Qs_hi[row][s0 >> 1] = make_uint4(h[0],h[1],h[2],h[3]);
        *(uint4*)&Qs_lo[row][s0 >> 1] = make_uint4(l[0],l[1],l[2],l[3]);
    }

    const float* KWb = g_KW + (size_t)bh * T_SEQ * NS;
    __half* Pb = g_P + ((size_t)bh * T_SEQ + i0) * T_SEQ;

    float sl0 = 0.0f, sl1 = 0.0f;

    for (int j0 = 0; j0 < T_SEQ; j0 += 128) {
        __syncthreads();
        #pragma unroll
        for (int rr = 0; rr < 2; rr++) {
            int row = (t >> 2) + rr * 64, s0 = (t & 3) * 8;
            const float* p = KWb + (size_t)(j0 + row) * NS + s0;
            float4 f0 = *(const float4*)p, f1 = *(const float4*)(p + 4);
            float fb[8] = {f0.x,f0.y,f0.z,f0.w,f1.x,f1.y,f1.z,f1.w};
            unsigned h[4], l[4];
            #pragma unroll
            for (int j = 0; j < 4; j++) split_pack_h(fb[2*j], fb[2*j+1], h[j], l[j]);
            *(uint4*)&Ks_hi[row][s0 >> 1] = make_uint4(h[0],h[1],h[2],h[3]);
            *(uint4*)&Ks_lo[row][s0 >> 1] = make_uint4(l[0],l[1],l[2],l[3]);
        }
        __syncthreads();

        float d[8][4];
        #pragma unroll
        for (int nt = 0; nt < 8; nt++)
            #pragma unroll
            for (int q = 0; q < 4; q++) d[nt][q] = 0.0f;

        #pragma unroll
        for (int p2 = 0; p2 < 2; p2++) {
            int rm = wm * 16 + g;
            unsigned ah[4], al[4];
            ah[0] = Qs_hi[rm][p2*8 + tig];     ah[1] = Qs_hi[rm + 8][p2*8 + tig];
            ah[2] = Qs_hi[rm][p2*8 + tig + 4]; ah[3] = Qs_hi[rm + 8][p2*8 + tig + 4];
            al[0] = Qs_lo[rm][p2*8 + tig];     al[1] = Qs_lo[rm + 8][p2*8 + tig];
            al[2] = Qs_lo[rm][p2*8 + tig + 4]; al[3] = Qs_lo[rm + 8][p2*8 + tig + 4];
            #pragma unroll
            for (int nt = 0; nt < 8; nt++) {
                int rn = wn * 64 + nt * 8 + g;
                unsigned kh0 = Ks_hi[rn][p2*8 + tig], kh1 = Ks_hi[rn][p2*8 + tig + 4];
                unsigned kl0 = Ks_lo[rn][p2*8 + tig], kl1 = Ks_lo[rn][p2*8 + tig + 4];
                mma_f16(d[nt], ah, kh0, kh1);
                mma_f16(d[nt], ah, kl0, kl1);
                mma_f16(d[nt], al, kh0, kh1);
            }
        }

        #pragma unroll
        for (int nt = 0; nt < 8; nt++) {
            float e0 = fast_exp(d[nt][0] * invT);
            float e1 = fast_exp(d[nt][1] * invT);
            float e2 = fast_exp(d[nt][2] * invT);
            float e3 = fast_exp(d[nt][3] * invT);
            sl0 += e0 + e1;  sl1 += e2 + e3;
            int r0 = wm * 16 + g, c = wn * 64 + nt * 8 + tig * 2;
            *(__half2*)&Pst[r0][c]     = __floats2half2_rn(e0, e1);
            *(__half2*)&Pst[r0 + 8][c] = __floats2half2_rn(e2, e3);
        }
        __syncthreads();

        #pragma unroll
        for (int r = 0; r < 8; r++) {
            int row = warp * 8 + r;
            uint2 v = *(uint2*)&Pst[row][lane * 4];
            *(uint2*)&Pb[(size_t)row * T_SEQ + j0 + lane * 4] = v;
        }
    }

    sl0 += __shfl_xor_sync(0xffffffffu, sl0, 1);
    sl0 += __shfl_xor_sync(0xffffffffu, sl0, 2);
    sl1 += __shfl_xor_sync(0xffffffffu, sl1, 1);
    sl1 += __shfl_xor_sync(0xffffffffu, sl1, 2);
    if (tig == 0) {
        sums_sm[wn][wm * 16 + g]     = sl0;
        sums_sm[wn][wm * 16 + g + 8] = sl1;
    }
    __syncthreads();
    if (t < 64)
        g_Sinv[(size_t)bh * T_SEQ + i0 + t] = 1.0f / (sums_sm[0][t] + sums_sm[1][t]);
}

// AV v2: O = (P@V)*Sinv. P fp16 direct, V fp16 2-term split. K-panel 32, 2 syncs.
__global__ void __launch_bounds__(256, 2) av_t_kernel()
{
    __shared__ unsigned As[128][20];                     // fp16 pairs, cols 0..15
    __shared__ unsigned Bs_hi[128][20], Bs_lo[128][20];

    int t = threadIdx.x, warp = t >> 5, lane = t & 31;
    int g = lane >> 2, tig = lane & 3;
    int wm = warp >> 1, wn = warp & 1;

    int bh = blockIdx.y;
    int m0 = blockIdx.x * 128;
    const __half* A = g_P + (size_t)bh * T_SEQ * T_SEQ;
    const float* B = g_V + (size_t)bh * T_SEQ * DH;

    int m_a = t >> 1, ca = (t & 1) * 16;      // 16 halves
    int n_bb = t & 127, kh = (t >> 7) * 16;

    float d[2][8][4];
    #pragma unroll
    for (int mt = 0; mt < 2; mt++)
        #pragma unroll
        for (int nt = 0; nt < 8; nt++)
            #pragma unroll
            for (int q = 0; q < 4; q++) d[mt][nt][q] = 0.0f;

    uint4 pa[2]; float b_r[16];
    {
        const __half* Ap = A + (size_t)(m0 + m_a) * T_SEQ + ca;
        pa[0] = *(const uint4*)Ap; pa[1] = *(const uint4*)(Ap + 8);
        const float* Bp = B + (size_t)kh * DH + n_bb;
        #pragma unroll
        for (int j = 0; j < 16; j++) b_r[j] = Bp[(size_t)j * DH];
    }

    for (int k0 = 0; k0 < T_SEQ; k0 += 32) {
        __syncthreads();
        {
            *(uint4*)&As[m_a][(ca>>1)]     = pa[0];
            *(uint4*)&As[m_a][(ca>>1) + 4] = pa[1];
            unsigned h0[4], l0[4], h1[4], l1[4];
            #pragma unroll
            for (int j = 0; j < 4; j++) split_pack_h(b_r[2*j],   b_r[2*j+1],   h0[j], l0[j]);
            #pragma unroll
            for (int j = 0; j < 4; j++) split_pack_h(b_r[8+2*j], b_r[8+2*j+1], h1[j], l1[j]);
            *(uint4*)&Bs_hi[n_bb][(kh>>1)]     = make_uint4(h0[0],h0[1],h0[2],h0[3]);
            *(uint4*)&Bs_hi[n_bb][(kh>>1) + 4] = make_uint4(h1[0],h1[1],h1[2],h1[3]);
            *(uint4*)&Bs_lo[n_bb][(kh>>1)]     = make_uint4(l0[0],l0[1],l0[2],l0[3]);
            *(uint4*)&Bs_lo[n_bb][(kh>>1) + 4] = make_uint4(l1[0],l1[1],l1[2],l1[3]);
        }
        __syncthreads();

        if (k0 + 32 < T_SEQ) {
            const __half* Ap = A + (size_t)(m0 + m_a) * T_SEQ + k0 + 32 + ca;
            pa[0] = *(const uint4*)Ap; pa[1] = *(const uint4*)(Ap + 8);
            const float* Bp = B + (size_t)(k0 + 32 + kh) * DH + n_bb;
            #pragma unroll
            for (int j = 0; j < 16; j++) b_r[j] = Bp[(size_t)j * DH];
        }

        #pragma unroll
        for (int half = 0; half < 2; half++) {
            int base = half * 8;
            unsigned a[2][4];
            #pragma unroll
            for (int mt = 0; mt < 2; mt++) {
                int rm = wm * 32 + mt * 16 + g;
                a[mt][0] = As[rm][base + tig];     a[mt][1] = As[rm + 8][base + tig];
                a[mt][2] = As[rm][base + tig + 4]; a[mt][3] = As[rm + 8][base + tig + 4];
            }
            #pragma unroll
            for (int nt = 0; nt < 8; nt++) {
                int rn = wn * 64 + nt * 8 + g;
                unsigned bh0 = Bs_hi[rn][base + tig], bh1 = Bs_hi[rn][base + tig + 4];
                unsigned bl0 = Bs_lo[rn][base + tig], bl1 = Bs_lo[rn][base + tig + 4];
                #pragma unroll
                for (int mt = 0; mt < 2; mt++) {
                    mma_f16(d[mt][nt], a[mt], bh0, bh1);
                    mma_f16(d[mt][nt], a[mt], bl0, bl1);
                }
            }
        }
    }

    int b = bh >> 3, h = bh & 7;
    #pragma unroll
    for (int mt = 0; mt < 2; mt++) {
        #pragma unroll
        for (int r = 0; r < 2; r++) {
            int m = m0 + wm * 32 + mt * 16 + g + r * 8;
            float inv = g_Sinv[(size_t)bh * T_SEQ + m];
            #pragma unroll
            for (int nt = 0; nt < 8; nt++) {
                int col = wn * 64 + nt * 8 + tig * 2;
                float* dst = &g_O[(size_t)(b * T_SEQ + m) * DMODEL + h * DH + col];
                dst[0] = d[mt][nt][r*2 + 0] * inv;
                dst[1] = d[mt][nt][r*2 + 1] * inv;
            }
        }
    }
}

// bhij(fp16) -> bijh(fp32) transpose + normalize
__global__ void __launch_bounds__(256) transpose_kernel(float* __restrict__ attn)
{
    __shared__ float p_sm[512 * 9];

    int bi = blockIdx.x;
    int b = bi >> 11, i = bi & 2047;
    int t = threadIdx.x, w = t >> 5, lane = t & 31;

    const __half* src = g_P + ((size_t)(b * NH + w) * T_SEQ + i) * T_SEQ;
    float inv = g_Sinv[(size_t)(b * NH + w) * T_SEQ + i];
    float* dst = attn + ((size_t)(b * T_SEQ + i)) * T_SEQ * NH;

    for (int c = 0; c < 4; c++) {
        #pragma unroll
        for (int r = 0; r < 8; r++) {
            int u = r * 32 + lane;
            __half2 v = *(const __half2*)&src[c * 512 + u * 2];
            float2 f = __half22float2(v);
            p_sm[(2*u)     * 9 + w] = f.x * inv;
            p_sm[(2*u + 1) * 9 + w] = f.y * inv;
        }
        __syncthreads();
        #pragma unroll
        for (int r = 0; r < 16; r++) {
            int u = r * 256 + t;
            dst[c * 4096 + u] = p_sm[(u >> 3) * 9 + (u & 7)];
        }
        __syncthreads();
    }
}

extern "C" void kernel_launch(void* const* d_in, const int* in_sizes, int n_in,
                              void* d_out, int out_size)
{
    const float* x       = (const float*)d_in[0];
    const float* Wqkv    = (const float*)d_in[1];
    const float* bqkv    = (const float*)d_in[2];
    const float* Wout    = (const float*)d_in[3];
    const float* bout    = (const float*)d_in[4];
    const float* centers = (const float*)d_in[5];
    const float* lsc     = (const float*)d_in[6];
    const float* lam     = (const float*)d_in[7];
    const float* temp    = (const float*)d_in[8];

    float* out  = (float*)d_out;
    float* attn = out + (size_t)NB * T_SEQ * DMODEL;

    gemm_t_kernel<0><<<dim3(3 * DMODEL / 128, (NB * T_SEQ) / 128), 256>>>(
        x, Wqkv, bqkv, nullptr, 3 * DMODEL, DMODEL);                         // 1

    weights_kernel<<<dim3((NB * NH * T_SEQ) / 8, 2), 256>>>(centers, lsc, lam); // 2

    logits_t_kernel<<<dim3(T_SEQ / 64, NB * NH), 256>>>(temp);               // 3

    av_t_kernel<<<dim3(T_SEQ / 128, NB * NH), 256>>>();                      // 4 <- profiled

    transpose_kernel<<<NB * T_SEQ, 256>>>(attn);                             // 5

    gemm_t_kernel<1><<<dim3(DMODEL / 128, (NB * T_SEQ) / 128), 256>>>(
        nullptr, Wout, bout, out, DMODEL, DMODEL);                           // 6
}